// round 15
// baseline (speedup 1.0000x reference)
#include <cuda_runtime.h>
#include <math.h>
#include <stdint.h>

#define BB 4
#define NN 4096
#define DD 1024
#define EE 64
#define CAP 80
#define NTOK (BB*NN)            // 16384
#define EC (EE*CAP)             // 5120
#define COMBINE_OFF ((size_t)NTOK*(size_t)EC)   // 83886080

// Eigen/XLA-CPU vectorized exp clamps its input at ln(FLT_MIN)
#define EXP_CLAMP_LO (-87.33654785156250f)

// ---------------- scratch (no allocs; zero-init; output kernel re-zeroes per replay) ----
__device__ int    g_idx12 [NTOK];            // idx1 | idx2<<8
__device__ float2 g_gate  [NTOK];            // (g1, g2)
__device__ unsigned short g_pos[2*NTOK];     // [2t]=pos1, [2t+1]=pos2
__device__ double g_psum  [BB*EE];           // sum of probs per (b,e)
__device__ double g_bal;
__device__ double g_zsum;

__device__ __forceinline__ float ftz(float v) {
    unsigned u = __float_as_uint(v);
    return ((u & 0x7F800000u) == 0u) ? 0.0f : v;
}

__device__ __forceinline__ uint32_t f2tf32(float v) {
    uint32_t r; asm("cvt.rna.tf32.f32 %0, %1;" : "=r"(r) : "f"(v)); return r;
}

__device__ __forceinline__ void mma_tf32(float* c, const uint32_t* a, uint32_t b0, uint32_t b1) {
    asm volatile("mma.sync.aligned.m16n8k8.row.col.f32.tf32.tf32.f32 "
        "{%0,%1,%2,%3}, {%4,%5,%6,%7}, {%8,%9}, {%0,%1,%2,%3};"
        : "+f"(c[0]), "+f"(c[1]), "+f"(c[2]), "+f"(c[3])
        : "r"(a[0]), "r"(a[1]), "r"(a[2]), "r"(a[3]), "r"(b0), "r"(b1));
}

// ---------------- kernel 1: tf32 4-pass GEMM + softmax + top-2 ----------------
// block = 128 threads = 4 warps; tile = 64 tokens x 64 experts; grid = 256.
// smem blob layout (uint32 entries): xs_hi[64][36] | xs_lo | wt_hi[64][36] (n-major) | wt_lo
#define XH 0
#define XL 2304
#define WH 4608
#define WL 6912
__global__ void gemm_softmax_kernel(const float* __restrict__ x,
                                    const float* __restrict__ w) {
    __shared__ uint32_t sb[9216];
    __shared__ float accs[64];
    int tid = threadIdx.x;
    int warp = tid >> 5;
    int lane = tid & 31;
    int tok0 = blockIdx.x * 64;

    // prefetch chunk 0
    float4 rx[4], rw[4];
#pragma unroll
    for (int r = 0; r < 4; r++) {
        int f = tid + 128 * r;
        rx[r] = *(const float4*)(x + (size_t)(tok0 + (f >> 3)) * DD + (f & 7) * 4);
        rw[r] = *(const float4*)(w + (size_t)(f >> 4) * EE + (f & 15) * 4);
    }

    float c[8][4];
#pragma unroll
    for (int n = 0; n < 8; n++)
#pragma unroll
        for (int i = 0; i < 4; i++) c[n][i] = 0.f;

    int ar0 = warp * 16 + (lane >> 2);     // A fragment rows
    int ak0 = lane & 3;                     // A/B fragment k within k8

    for (int t = 0; t < DD / 32; t++) {
        __syncthreads();
        // store chunk to smem with hi/lo tf32 split
#pragma unroll
        for (int r = 0; r < 4; r++) {
            int f = tid + 128 * r;
            int xrow = f >> 3, xq = f & 7;
            int krow = f >> 4, qn = f & 15;
            const float* pv = (const float*)&rx[r];
            const float* pw = (const float*)&rw[r];
#pragma unroll
            for (int cc = 0; cc < 4; cc++) {
                uint32_t hi = f2tf32(pv[cc]);
                sb[XH + xrow * 36 + xq * 4 + cc] = hi;
                sb[XL + xrow * 36 + xq * 4 + cc] = f2tf32(pv[cc] - __uint_as_float(hi));
                uint32_t whi = f2tf32(pw[cc]);
                sb[WH + (qn * 4 + cc) * 36 + krow] = whi;
                sb[WL + (qn * 4 + cc) * 36 + krow] = f2tf32(pw[cc] - __uint_as_float(whi));
            }
        }
        __syncthreads();

        if (t + 1 < DD / 32) {             // prefetch next chunk
            int kk = (t + 1) * 32;
#pragma unroll
            for (int r = 0; r < 4; r++) {
                int f = tid + 128 * r;
                rx[r] = *(const float4*)(x + (size_t)(tok0 + (f >> 3)) * DD + kk + (f & 7) * 4);
                rw[r] = *(const float4*)(w + (size_t)(kk + (f >> 4)) * EE + (f & 15) * 4);
            }
        }

#pragma unroll
        for (int k8 = 0; k8 < 4; k8++) {
            int kb = k8 * 8;
            uint32_t ah[4], al[4];
            ah[0] = sb[XH + ar0 * 36 + kb + ak0];
            ah[1] = sb[XH + (ar0 + 8) * 36 + kb + ak0];
            ah[2] = sb[XH + ar0 * 36 + kb + ak0 + 4];
            ah[3] = sb[XH + (ar0 + 8) * 36 + kb + ak0 + 4];
            al[0] = sb[XL + ar0 * 36 + kb + ak0];
            al[1] = sb[XL + (ar0 + 8) * 36 + kb + ak0];
            al[2] = sb[XL + ar0 * 36 + kb + ak0 + 4];
            al[3] = sb[XL + (ar0 + 8) * 36 + kb + ak0 + 4];
#pragma unroll
            for (int nt = 0; nt < 8; nt++) {
                int nr = nt * 8 + (lane >> 2);
                uint32_t bh0 = sb[WH + nr * 36 + kb + ak0];
                uint32_t bh1 = sb[WH + nr * 36 + kb + ak0 + 4];
                uint32_t bl0 = sb[WL + nr * 36 + kb + ak0];
                uint32_t bl1 = sb[WL + nr * 36 + kb + ak0 + 4];
                mma_tf32(c[nt], ah, bh0, bh1);
                mma_tf32(c[nt], al, bh0, bh1);
                mma_tf32(c[nt], ah, bl0, bl1);
                mma_tf32(c[nt], al, bl0, bl1);
            }
        }
    }

    // ---------------- epilogue: fragments -> smem logits (stride 65) ----------------
    __syncthreads();
    float* lg = (float*)sb;                // 64 x 65 floats fits in the blob
    {
        int row0 = warp * 16 + (lane >> 2);
        int col = (lane & 3) * 2;
#pragma unroll
        for (int nt = 0; nt < 8; nt++) {
            lg[row0 * 65 + nt * 8 + col]           = c[nt][0];
            lg[row0 * 65 + nt * 8 + col + 1]       = c[nt][1];
            lg[(row0 + 8) * 65 + nt * 8 + col]     = c[nt][2];
            lg[(row0 + 8) * 65 + nt * 8 + col + 1] = c[nt][3];
        }
    }
    if (tid < 64) accs[tid] = 0.f;
    __syncthreads();

    double zacc = 0.0;
#pragma unroll 4
    for (int u = 0; u < 16; u++) {
        int tt = warp * 16 + u;
        float v0 = lg[tt * 65 + lane];
        float v1 = lg[tt * 65 + lane + 32];

        float m = fmaxf(v0, v1);
#pragma unroll
        for (int o = 16; o; o >>= 1) m = fmaxf(m, __shfl_xor_sync(0xffffffffu, m, o));

        float e0 = expf(fmaxf(v0 - m, EXP_CLAMP_LO));
        float e1 = expf(fmaxf(v1 - m, EXP_CLAMP_LO));
        float s = e0 + e1;
#pragma unroll
        for (int o = 16; o; o >>= 1) s += __shfl_xor_sync(0xffffffffu, s, o);

        float p0 = ftz(e0 / s);
        float p1 = ftz(e1 / s);

        atomicAdd(&accs[lane],      p0);
        atomicAdd(&accs[lane + 32], p1);

        unsigned long long k0 = ((unsigned long long)__float_as_uint(p0) << 32) | (unsigned)(63 - lane);
        unsigned long long k1 = ((unsigned long long)__float_as_uint(p1) << 32) | (unsigned)(63 - (lane + 32));

        unsigned long long kt = (k0 > k1) ? k0 : k1;
#pragma unroll
        for (int o = 16; o; o >>= 1) {
            unsigned long long ko = __shfl_xor_sync(0xffffffffu, kt, o);
            if (ko > kt) kt = ko;
        }
        int ri = 63 - (int)(kt & 0x3F);

        unsigned long long q0 = (lane        == ri) ? 0ULL : k0;
        unsigned long long q1 = ((lane + 32) == ri) ? 0ULL : k1;
        unsigned long long kt2 = (q0 > q1) ? q0 : q1;
#pragma unroll
        for (int o = 16; o; o >>= 1) {
            unsigned long long ko = __shfl_xor_sync(0xffffffffu, kt2, o);
            if (ko > kt2) kt2 = ko;
        }
        int ri2 = 63 - (int)(kt2 & 0x3F);

        if (lane == 0) {
            zacc += (double)m + log((double)s);
            float pv1 = __uint_as_float((unsigned)(kt  >> 32));
            float pv2 = __uint_as_float((unsigned)(kt2 >> 32));
            float denom = pv1 + pv2 + 1e-9f;
            g_idx12[tok0 + tt] = ri | (ri2 << 8);
            g_gate[tok0 + tt] = make_float2(ftz(pv1 / denom), ftz(pv2 / denom));
        }
    }

    if (lane == 0) atomicAdd(&g_zsum, zacc);
    __syncthreads();
    if (tid < 64) {
        int b = tok0 >> 12;
        atomicAdd(&g_psum[b * EE + tid], (double)accs[tid]);
    }
}

// ---------------- kernel 2: per-(batch, expert) prefix scan ----------------
__global__ void scan_kernel() {
    __shared__ int sh[256];
    int b = blockIdx.x >> 6;
    int e = blockIdx.x & 63;
    int tid = threadIdx.x;
    int base = b * NN;
    int n0 = tid * 16;

    int idx[16];
#pragma unroll
    for (int q = 0; q < 4; q++) {
        int4 v = *(const int4*)&g_idx12[base + n0 + q * 4];
        idx[q*4+0] = v.x; idx[q*4+1] = v.y; idx[q*4+2] = v.z; idx[q*4+3] = v.w;
    }

    int c1 = 0, c2 = 0;
    unsigned m1bits = 0, m2bits = 0;
#pragma unroll
    for (int j = 0; j < 16; j++) {
        if ((idx[j] & 0xFF) == e) { c1++; m1bits |= (1u << j); }
        if ((idx[j] >> 8)   == e) { c2++; m2bits |= (1u << j); }
    }

    int incl1, incl2, tot1;
    __syncthreads(); sh[tid] = c1; __syncthreads();
#pragma unroll
    for (int o = 1; o < 256; o <<= 1) {
        int t = (tid >= o) ? sh[tid - o] : 0;
        __syncthreads(); sh[tid] += t; __syncthreads();
    }
    incl1 = sh[tid]; tot1 = sh[255];
    __syncthreads(); sh[tid] = c2; __syncthreads();
#pragma unroll
    for (int o = 1; o < 256; o <<= 1) {
        int t = (tid >= o) ? sh[tid - o] : 0;
        __syncthreads(); sh[tid] += t; __syncthreads();
    }
    incl2 = sh[tid];

    int off1 = incl1 - c1;
    int off2 = incl2 - c2;
#pragma unroll
    for (int j = 0; j < 16; j++) {
        if ((m1bits >> j) & 1u) { g_pos[2*(base + n0 + j)]     = (unsigned short)off1; off1++; }
        if ((m2bits >> j) & 1u) { g_pos[2*(base + n0 + j) + 1] = (unsigned short)off2; off2++; }
    }

    if (tid == 0) {
        double part = (g_psum[b * EE + e] / (double)NN) * ((double)tot1 / (double)NN);
        atomicAdd(&g_bal, part);
    }
}

// ---------------- kernel 3: fill with inline scatter (R6-proven) + scalars + reset ----------------
__global__ void output_kernel(float* __restrict__ out) {
    int token = blockIdx.x;
    int tid = threadIdx.x;

    int idx12 = g_idx12[token];
    unsigned short p1 = g_pos[2*token];
    unsigned short p2 = g_pos[2*token + 1];
    float2 g = g_gate[token];
    int e1 = idx12 & 0xFF, e2 = idx12 >> 8;
    float v1 = (p1 < CAP) ? g.x : 0.f;
    float v2 = (p2 < CAP) ? g.y : 0.f;
    bool nz1 = (__float_as_int(v1) != 0);
    bool nz2 = (__float_as_int(v2) != 0);
    int off1 = e1 * CAP + p1;
    int off2 = e2 * CAP + p2;

    size_t dbase = (size_t)token * EC;
    size_t cbase = COMBINE_OFF + dbase;

#pragma unroll
    for (int it = 0; it < 5; it++) {
        int i0 = (it * 256 + tid) * 4;
        float4 cc = make_float4(0.f, 0.f, 0.f, 0.f);
        float4 dd = make_float4(0.f, 0.f, 0.f, 0.f);
        if (nz1 && off1 >= i0 && off1 < i0 + 4) {
            ((float*)&cc)[off1 - i0] = v1;
            ((float*)&dd)[off1 - i0] = 1.f;
        }
        if (nz2 && off2 >= i0 && off2 < i0 + 4) {
            ((float*)&cc)[off2 - i0] = v2;
            ((float*)&dd)[off2 - i0] = 1.f;
        }
        __stcs((float4*)&out[dbase + i0], dd);
        __stcs((float4*)&out[cbase + i0], cc);
    }

    if (blockIdx.x == 0 && tid == 0) {
        out[2 * COMBINE_OFF]     = (float)(g_bal * (double)EE / (double)BB);
        out[2 * COMBINE_OFF + 1] = (float)(g_zsum / (double)BB);
        // reset accumulators for the next graph replay
        g_bal = 0.0; g_zsum = 0.0;
        for (int i = 0; i < BB*EE; i++) g_psum[i] = 0.0;
    }
}

extern "C" void kernel_launch(void* const* d_in, const int* in_sizes, int n_in,
                              void* d_out, int out_size) {
    const float* x = (const float*)d_in[0];
    const float* w = (const float*)d_in[1];
    float* out = (float*)d_out;

    gemm_softmax_kernel<<<NTOK / 64, 128>>>(x, w);
    scan_kernel<<<BB * EE, 256>>>();
    output_kernel<<<NTOK, 256>>>(out);
}

// round 16
// speedup vs baseline: 1.0482x; 1.0482x over previous
#include <cuda_runtime.h>
#include <math.h>
#include <stdint.h>

#define BB 4
#define NN 4096
#define DD 1024
#define EE 64
#define CAP 80
#define NTOK (BB*NN)            // 16384
#define EC (EE*CAP)             // 5120
#define COMBINE_OFF ((size_t)NTOK*(size_t)EC)   // 83886080

// Eigen/XLA-CPU vectorized exp clamps its input at ln(FLT_MIN)
#define EXP_CLAMP_LO (-87.33654785156250f)

// ---------------- scratch (no allocs; zero-init; output kernel re-zeroes per replay) ----
__device__ int    g_idx12 [NTOK];            // idx1 | idx2<<8
__device__ float2 g_gate  [NTOK];            // (g1, g2)
__device__ unsigned short g_pos[2*NTOK];     // [2t]=pos1, [2t+1]=pos2
__device__ double g_psum  [BB*EE];           // sum of probs per (b,e)
__device__ double g_bal;
__device__ double g_zsum;

__device__ __forceinline__ float ftz(float v) {
    unsigned u = __float_as_uint(v);
    return ((u & 0x7F800000u) == 0u) ? 0.0f : v;
}

__device__ __forceinline__ uint32_t f2tf32(float v) {
    uint32_t r; asm("cvt.rna.tf32.f32 %0, %1;" : "=r"(r) : "f"(v)); return r;
}

__device__ __forceinline__ void mma_tf32(float* c, const uint32_t* a, uint32_t b0, uint32_t b1) {
    asm volatile("mma.sync.aligned.m16n8k8.row.col.f32.tf32.tf32.f32 "
        "{%0,%1,%2,%3}, {%4,%5,%6,%7}, {%8,%9}, {%0,%1,%2,%3};"
        : "+f"(c[0]), "+f"(c[1]), "+f"(c[2]), "+f"(c[3])
        : "r"(a[0]), "r"(a[1]), "r"(a[2]), "r"(a[3]), "r"(b0), "r"(b1));
}

// ---------------- kernel 1: tf32 3-pass GEMM + softmax + top-2 ----------------
// block = 256 threads = 8 warps; tile = 64 tok x 64 exp; warp owns m16 x n32.
// smem blob (uint32): XH[64][36] | XL | WH[64][36] (n-major) | WL
#define XH 0
#define XL 2304
#define WH 4608
#define WL 6912
__global__ void __launch_bounds__(256)
gemm_softmax_kernel(const float* __restrict__ x, const float* __restrict__ w) {
    __shared__ uint32_t sb[9216];
    __shared__ float accs[64];
    int tid = threadIdx.x;
    int warp = tid >> 5;
    int lane = tid & 31;
    int tok0 = blockIdx.x * 64;

    int mrow = (warp >> 1) * 16;           // warp's token rows
    int ncol = (warp & 1) * 32;            // warp's expert cols
    int ar0 = mrow + (lane >> 2);
    int ak0 = lane & 3;

    // prefetch chunk 0: x 512 float4, w 512 float4 -> 2 each per thread
    float4 rx[2], rw[2];
#pragma unroll
    for (int r = 0; r < 2; r++) {
        int f = tid + 256 * r;
        rx[r] = *(const float4*)(x + (size_t)(tok0 + (f >> 3)) * DD + (f & 7) * 4);
        rw[r] = *(const float4*)(w + (size_t)(f >> 4) * EE + (f & 15) * 4);
    }

    float c[4][4];
#pragma unroll
    for (int n = 0; n < 4; n++)
#pragma unroll
        for (int i = 0; i < 4; i++) c[n][i] = 0.f;

    for (int t = 0; t < DD / 32; t++) {
        __syncthreads();
#pragma unroll
        for (int r = 0; r < 2; r++) {
            int f = tid + 256 * r;
            int xrow = f >> 3, xq = f & 7;
            int krow = f >> 4, qn = f & 15;
            const float* pv = (const float*)&rx[r];
            const float* pw = (const float*)&rw[r];
#pragma unroll
            for (int cc = 0; cc < 4; cc++) {
                uint32_t hi = f2tf32(pv[cc]);
                sb[XH + xrow * 36 + xq * 4 + cc] = hi;
                sb[XL + xrow * 36 + xq * 4 + cc] = f2tf32(pv[cc] - __uint_as_float(hi));
                uint32_t whi = f2tf32(pw[cc]);
                sb[WH + (qn * 4 + cc) * 36 + krow] = whi;
                sb[WL + (qn * 4 + cc) * 36 + krow] = f2tf32(pw[cc] - __uint_as_float(whi));
            }
        }
        __syncthreads();

        if (t + 1 < DD / 32) {             // prefetch next chunk
            int kk = (t + 1) * 32;
#pragma unroll
            for (int r = 0; r < 2; r++) {
                int f = tid + 256 * r;
                rx[r] = *(const float4*)(x + (size_t)(tok0 + (f >> 3)) * DD + kk + (f & 7) * 4);
                rw[r] = *(const float4*)(w + (size_t)(kk + (f >> 4)) * EE + (f & 15) * 4);
            }
        }

#pragma unroll
        for (int k8 = 0; k8 < 4; k8++) {
            int kb = k8 * 8;
            uint32_t ah[4], al[4];
            ah[0] = sb[XH + ar0 * 36 + kb + ak0];
            ah[1] = sb[XH + (ar0 + 8) * 36 + kb + ak0];
            ah[2] = sb[XH + ar0 * 36 + kb + ak0 + 4];
            ah[3] = sb[XH + (ar0 + 8) * 36 + kb + ak0 + 4];
            al[0] = sb[XL + ar0 * 36 + kb + ak0];
            al[1] = sb[XL + (ar0 + 8) * 36 + kb + ak0];
            al[2] = sb[XL + ar0 * 36 + kb + ak0 + 4];
            al[3] = sb[XL + (ar0 + 8) * 36 + kb + ak0 + 4];
#pragma unroll
            for (int nt = 0; nt < 4; nt++) {
                int nr = ncol + nt * 8 + (lane >> 2);
                uint32_t bh0 = sb[WH + nr * 36 + kb + ak0];
                uint32_t bh1 = sb[WH + nr * 36 + kb + ak0 + 4];
                uint32_t bl0 = sb[WL + nr * 36 + kb + ak0];
                uint32_t bl1 = sb[WL + nr * 36 + kb + ak0 + 4];
                mma_tf32(c[nt], ah, bh0, bh1);   // hi*hi
                mma_tf32(c[nt], al, bh0, bh1);   // lo*hi
                mma_tf32(c[nt], ah, bl0, bl1);   // hi*lo  (lo*lo dropped: ~2e-6 abs)
            }
        }
    }

    // ---------------- epilogue: fragments -> smem logits (stride 65) ----------------
    __syncthreads();
    float* lg = (float*)sb;                // 64 x 65 floats fits in the blob
    {
        int row0 = mrow + (lane >> 2);
        int col0 = ncol + (lane & 3) * 2;
#pragma unroll
        for (int nt = 0; nt < 4; nt++) {
            lg[row0 * 65 + col0 + nt * 8]           = c[nt][0];
            lg[row0 * 65 + col0 + nt * 8 + 1]       = c[nt][1];
            lg[(row0 + 8) * 65 + col0 + nt * 8]     = c[nt][2];
            lg[(row0 + 8) * 65 + col0 + nt * 8 + 1] = c[nt][3];
        }
    }
    if (tid < 64) accs[tid] = 0.f;
    __syncthreads();

    double zacc = 0.0;
#pragma unroll 4
    for (int u = 0; u < 8; u++) {
        int tt = warp * 8 + u;             // 8 warps x 8 tokens
        float v0 = lg[tt * 65 + lane];
        float v1 = lg[tt * 65 + lane + 32];

        float m = fmaxf(v0, v1);
#pragma unroll
        for (int o = 16; o; o >>= 1) m = fmaxf(m, __shfl_xor_sync(0xffffffffu, m, o));

        float e0 = expf(fmaxf(v0 - m, EXP_CLAMP_LO));
        float e1 = expf(fmaxf(v1 - m, EXP_CLAMP_LO));
        float s = e0 + e1;
#pragma unroll
        for (int o = 16; o; o >>= 1) s += __shfl_xor_sync(0xffffffffu, s, o);

        float p0 = ftz(e0 / s);
        float p1 = ftz(e1 / s);

        atomicAdd(&accs[lane],      p0);
        atomicAdd(&accs[lane + 32], p1);

        unsigned long long k0 = ((unsigned long long)__float_as_uint(p0) << 32) | (unsigned)(63 - lane);
        unsigned long long k1 = ((unsigned long long)__float_as_uint(p1) << 32) | (unsigned)(63 - (lane + 32));

        unsigned long long kt = (k0 > k1) ? k0 : k1;
#pragma unroll
        for (int o = 16; o; o >>= 1) {
            unsigned long long ko = __shfl_xor_sync(0xffffffffu, kt, o);
            if (ko > kt) kt = ko;
        }
        int ri = 63 - (int)(kt & 0x3F);

        unsigned long long q0 = (lane        == ri) ? 0ULL : k0;
        unsigned long long q1 = ((lane + 32) == ri) ? 0ULL : k1;
        unsigned long long kt2 = (q0 > q1) ? q0 : q1;
#pragma unroll
        for (int o = 16; o; o >>= 1) {
            unsigned long long ko = __shfl_xor_sync(0xffffffffu, kt2, o);
            if (ko > kt2) kt2 = ko;
        }
        int ri2 = 63 - (int)(kt2 & 0x3F);

        if (lane == 0) {
            zacc += (double)m + log((double)s);
            float pv1 = __uint_as_float((unsigned)(kt  >> 32));
            float pv2 = __uint_as_float((unsigned)(kt2 >> 32));
            float denom = pv1 + pv2 + 1e-9f;
            g_idx12[tok0 + tt] = ri | (ri2 << 8);
            g_gate[tok0 + tt] = make_float2(ftz(pv1 / denom), ftz(pv2 / denom));
        }
    }

    if (lane == 0) atomicAdd(&g_zsum, zacc);
    __syncthreads();
    if (tid < 64) {
        int b = tok0 >> 12;
        atomicAdd(&g_psum[b * EE + tid], (double)accs[tid]);
    }
}

// ---------------- kernel 2: per-(batch, expert) prefix scan ----------------
__global__ void scan_kernel() {
    __shared__ int sh[256];
    int b = blockIdx.x >> 6;
    int e = blockIdx.x & 63;
    int tid = threadIdx.x;
    int base = b * NN;
    int n0 = tid * 16;

    int idx[16];
#pragma unroll
    for (int q = 0; q < 4; q++) {
        int4 v = *(const int4*)&g_idx12[base + n0 + q * 4];
        idx[q*4+0] = v.x; idx[q*4+1] = v.y; idx[q*4+2] = v.z; idx[q*4+3] = v.w;
    }

    int c1 = 0, c2 = 0;
    unsigned m1bits = 0, m2bits = 0;
#pragma unroll
    for (int j = 0; j < 16; j++) {
        if ((idx[j] & 0xFF) == e) { c1++; m1bits |= (1u << j); }
        if ((idx[j] >> 8)   == e) { c2++; m2bits |= (1u << j); }
    }

    int incl1, incl2, tot1;
    __syncthreads(); sh[tid] = c1; __syncthreads();
#pragma unroll
    for (int o = 1; o < 256; o <<= 1) {
        int t = (tid >= o) ? sh[tid - o] : 0;
        __syncthreads(); sh[tid] += t; __syncthreads();
    }
    incl1 = sh[tid]; tot1 = sh[255];
    __syncthreads(); sh[tid] = c2; __syncthreads();
#pragma unroll
    for (int o = 1; o < 256; o <<= 1) {
        int t = (tid >= o) ? sh[tid - o] : 0;
        __syncthreads(); sh[tid] += t; __syncthreads();
    }
    incl2 = sh[tid];

    int off1 = incl1 - c1;
    int off2 = incl2 - c2;
#pragma unroll
    for (int j = 0; j < 16; j++) {
        if ((m1bits >> j) & 1u) { g_pos[2*(base + n0 + j)]     = (unsigned short)off1; off1++; }
        if ((m2bits >> j) & 1u) { g_pos[2*(base + n0 + j) + 1] = (unsigned short)off2; off2++; }
    }

    if (tid == 0) {
        double part = (g_psum[b * EE + e] / (double)NN) * ((double)tot1 / (double)NN);
        atomicAdd(&g_bal, part);
    }
}

// ---------------- kernel 3: fill with inline scatter + scalars + reset ----------------
__global__ void output_kernel(float* __restrict__ out) {
    int token = blockIdx.x;
    int tid = threadIdx.x;

    int idx12 = g_idx12[token];
    unsigned short p1 = g_pos[2*token];
    unsigned short p2 = g_pos[2*token + 1];
    float2 g = g_gate[token];
    int e1 = idx12 & 0xFF, e2 = idx12 >> 8;
    float v1 = (p1 < CAP) ? g.x : 0.f;
    float v2 = (p2 < CAP) ? g.y : 0.f;
    bool nz1 = (__float_as_int(v1) != 0);
    bool nz2 = (__float_as_int(v2) != 0);
    int off1 = e1 * CAP + p1;
    int off2 = e2 * CAP + p2;

    size_t dbase = (size_t)token * EC;
    size_t cbase = COMBINE_OFF + dbase;

#pragma unroll
    for (int it = 0; it < 5; it++) {
        int i0 = (it * 256 + tid) * 4;
        float4 cc = make_float4(0.f, 0.f, 0.f, 0.f);
        float4 dd = make_float4(0.f, 0.f, 0.f, 0.f);
        if (nz1 && off1 >= i0 && off1 < i0 + 4) {
            ((float*)&cc)[off1 - i0] = v1;
            ((float*)&dd)[off1 - i0] = 1.f;
        }
        if (nz2 && off2 >= i0 && off2 < i0 + 4) {
            ((float*)&cc)[off2 - i0] = v2;
            ((float*)&dd)[off2 - i0] = 1.f;
        }
        __stcs((float4*)&out[dbase + i0], dd);
        __stcs((float4*)&out[cbase + i0], cc);
    }

    if (blockIdx.x == 0 && tid == 0) {
        out[2 * COMBINE_OFF]     = (float)(g_bal * (double)EE / (double)BB);
        out[2 * COMBINE_OFF + 1] = (float)(g_zsum / (double)BB);
        g_bal = 0.0; g_zsum = 0.0;
        for (int i = 0; i < BB*EE; i++) g_psum[i] = 0.0;
    }
}

extern "C" void kernel_launch(void* const* d_in, const int* in_sizes, int n_in,
                              void* d_out, int out_size) {
    const float* x = (const float*)d_in[0];
    const float* w = (const float*)d_in[1];
    float* out = (float*)d_out;

    gemm_softmax_kernel<<<NTOK / 64, 256>>>(x, w);
    scan_kernel<<<BB * EE, 256>>>();
    output_kernel<<<NTOK, 256>>>(out);
}